// round 2
// baseline (speedup 1.0000x reference)
#include <cuda_runtime.h>
#include <math.h>

#define BB   4
#define SS   2048
#define HIDD 1280
#define NHH  16
#define NKVV 4
#define HDD  80
#define QKVD 1920
#define MR   (BB*SS)      // 8192
#define NEGMASK (-2.3819763e38f)

// ---- scratch (no allocations allowed: device globals) ----
__device__ float g_q[(size_t)BB*NHH*SS*HDD];     // [B,H,S,D]  (pre-scaled)
__device__ float g_k[(size_t)BB*NKVV*SS*HDD];    // [B,KVH,S,D]
__device__ float g_v[(size_t)BB*NKVV*SS*HDD];    // [B,KVH,S,D]
__device__ float g_attn[(size_t)BB*SS*HIDD];     // [B,S,H*D]
__device__ float g_qscale[HDD];

// ---------------------------------------------------------------------------
__global__ void qscale_kernel(const float* __restrict__ scaling)
{
    int d = threadIdx.x;
    if (d < HDD) {
        float x  = scaling[d];
        float sp = (x > 20.f) ? x : log1pf(expf(x));   // softplus, stable
        g_qscale[d] = 1.442695041f * rsqrtf((float)HDD) * sp;
    }
}

// ---------------------------------------------------------------------------
// QKV GEMM: out[m,n] = sum_k A[m,k]*W[n,k] + b[n], scattered to g_q/g_k/g_v.
// 128x128 block tile, BK=8, 8x8 per thread, 256 threads.
__global__ __launch_bounds__(256) void qkv_gemm_kernel(
    const float* __restrict__ A, const float* __restrict__ W,
    const float* __restrict__ bias)
{
    __shared__ float As[8][128];
    __shared__ float Bs[8][128];
    const int tid = threadIdx.x;
    const int tx  = tid & 15;
    const int ty  = tid >> 4;
    const int rowBase = blockIdx.y * 128;
    const int colBase = blockIdx.x * 128;
    const int lRow = tid >> 1;
    const int lCol = (tid & 1) * 4;

    float acc[8][8];
#pragma unroll
    for (int i = 0; i < 8; i++)
#pragma unroll
        for (int j = 0; j < 8; j++) acc[i][j] = 0.f;

    const float* Ag = A + (size_t)(rowBase + lRow) * HIDD + lCol;
    const float* Wg = W + (size_t)(colBase + lRow) * HIDD + lCol;

    for (int k0 = 0; k0 < HIDD; k0 += 8) {
        float4 av = *(const float4*)(Ag + k0);
        float4 bv = *(const float4*)(Wg + k0);
        As[lCol+0][lRow] = av.x; As[lCol+1][lRow] = av.y;
        As[lCol+2][lRow] = av.z; As[lCol+3][lRow] = av.w;
        Bs[lCol+0][lRow] = bv.x; Bs[lCol+1][lRow] = bv.y;
        Bs[lCol+2][lRow] = bv.z; Bs[lCol+3][lRow] = bv.w;
        __syncthreads();
#pragma unroll
        for (int k = 0; k < 8; k++) {
            float4 a0 = *(const float4*)&As[k][ty*8];
            float4 a1 = *(const float4*)&As[k][ty*8+4];
            float4 b0 = *(const float4*)&Bs[k][tx*8];
            float4 b1 = *(const float4*)&Bs[k][tx*8+4];
            float a[8] = {a0.x,a0.y,a0.z,a0.w,a1.x,a1.y,a1.z,a1.w};
            float b[8] = {b0.x,b0.y,b0.z,b0.w,b1.x,b1.y,b1.z,b1.w};
#pragma unroll
            for (int i = 0; i < 8; i++)
#pragma unroll
                for (int j = 0; j < 8; j++)
                    acc[i][j] = fmaf(a[i], b[j], acc[i][j]);
        }
        __syncthreads();
    }

    // epilogue: scatter to q (scaled) / k / v
#pragma unroll
    for (int i = 0; i < 8; i++) {
        int m  = rowBase + ty*8 + i;
        int bb = m >> 11;          // / 2048
        int s  = m & 2047;
#pragma unroll
        for (int j = 0; j < 8; j++) {
            int   n = colBase + tx*8 + j;
            float v = acc[i][j] + bias[n];
            if (n < 1280) {
                int h = n / HDD, d = n - h*HDD;
                g_q[(((size_t)(bb*NHH + h))*SS + s)*HDD + d] = v * g_qscale[d];
            } else if (n < 1600) {
                int c = n - 1280; int h = c / HDD, d = c - h*HDD;
                g_k[(((size_t)(bb*NKVV + h))*SS + s)*HDD + d] = v;
            } else {
                int c = n - 1600; int h = c / HDD, d = c - h*HDD;
                g_v[(((size_t)(bb*NKVV + h))*SS + s)*HDD + d] = v;
            }
        }
    }
}

// ---------------------------------------------------------------------------
// O GEMM: out[m,n] = sum_k g_attn[m,k]*o_w[n,k] + o_b[n]
__global__ __launch_bounds__(256) void o_gemm_kernel(
    float* __restrict__ out, const float* __restrict__ W,
    const float* __restrict__ bias)
{
    __shared__ float As[8][128];
    __shared__ float Bs[8][128];
    const int tid = threadIdx.x;
    const int tx  = tid & 15;
    const int ty  = tid >> 4;
    const int rowBase = blockIdx.y * 128;
    const int colBase = blockIdx.x * 128;
    const int lRow = tid >> 1;
    const int lCol = (tid & 1) * 4;

    float acc[8][8];
#pragma unroll
    for (int i = 0; i < 8; i++)
#pragma unroll
        for (int j = 0; j < 8; j++) acc[i][j] = 0.f;

    const float* Ag = g_attn + (size_t)(rowBase + lRow) * HIDD + lCol;
    const float* Wg = W + (size_t)(colBase + lRow) * HIDD + lCol;

    for (int k0 = 0; k0 < HIDD; k0 += 8) {
        float4 av = *(const float4*)(Ag + k0);
        float4 bv = *(const float4*)(Wg + k0);
        As[lCol+0][lRow] = av.x; As[lCol+1][lRow] = av.y;
        As[lCol+2][lRow] = av.z; As[lCol+3][lRow] = av.w;
        Bs[lCol+0][lRow] = bv.x; Bs[lCol+1][lRow] = bv.y;
        Bs[lCol+2][lRow] = bv.z; Bs[lCol+3][lRow] = bv.w;
        __syncthreads();
#pragma unroll
        for (int k = 0; k < 8; k++) {
            float4 a0 = *(const float4*)&As[k][ty*8];
            float4 a1 = *(const float4*)&As[k][ty*8+4];
            float4 b0 = *(const float4*)&Bs[k][tx*8];
            float4 b1 = *(const float4*)&Bs[k][tx*8+4];
            float a[8] = {a0.x,a0.y,a0.z,a0.w,a1.x,a1.y,a1.z,a1.w};
            float b[8] = {b0.x,b0.y,b0.z,b0.w,b1.x,b1.y,b1.z,b1.w};
#pragma unroll
            for (int i = 0; i < 8; i++)
#pragma unroll
                for (int j = 0; j < 8; j++)
                    acc[i][j] = fmaf(a[i], b[j], acc[i][j]);
        }
        __syncthreads();
    }
#pragma unroll
    for (int i = 0; i < 8; i++) {
        int m = rowBase + ty*8 + i;
#pragma unroll
        for (int j = 0; j < 8; j++) {
            int n = colBase + tx*8 + j;
            out[(size_t)m*HIDD + n] = acc[i][j] + bias[n];
        }
    }
}

// ---------------------------------------------------------------------------
// Flash attention, fp32, 64x64 tiles, online softmax, causal.
// grid: (S/64, NH, B), 256 threads (16x16).
#define SQ_STRIDE 81
#define SP_STRIDE 65
#define ATT_SMEM_FLOATS (3*64*SQ_STRIDE + 64*SP_STRIDE + 3*64)
#define ATT_SMEM_BYTES  (ATT_SMEM_FLOATS * 4)

__global__ __launch_bounds__(256) void attn_kernel()
{
    extern __shared__ float sm[];
    float* sQ = sm;                       // 64 x 81
    float* sK = sQ + 64*SQ_STRIDE;        // 64 x 81
    float* sV = sK + 64*SQ_STRIDE;        // 64 x 81
    float* sP = sV + 64*SQ_STRIDE;        // 64 x 65
    float* sM = sP + 64*SP_STRIDE;        // 64
    float* sL = sM + 64;                  // 64
    float* sA = sL + 64;                  // 64

    const int tid = threadIdx.x;
    const int tx  = tid & 15;
    const int ty  = tid >> 4;
    const int qb  = blockIdx.x;
    const int h   = blockIdx.y;
    const int b   = blockIdx.z;
    const int kvh = h >> 2;               // GQA: 4 query heads per kv head

    const float* Qg    = g_q + (((size_t)(b*NHH  + h  ))*SS + qb*64) * HDD;
    const float* Kbase = g_k + (((size_t)(b*NKVV + kvh))*SS) * HDD;
    const float* Vbase = g_v + (((size_t)(b*NKVV + kvh))*SS) * HDD;

    // load Q tile (5120 floats, 20 per thread, float4)
#pragma unroll
    for (int t = 0; t < 5; t++) {
        int lin = tid + t*256;            // float4 index 0..1279
        int r = lin / 20, cv = lin % 20;
        float4 v = *(const float4*)(Qg + r*HDD + cv*4);
        float* dst = &sQ[r*SQ_STRIDE + cv*4];
        dst[0]=v.x; dst[1]=v.y; dst[2]=v.z; dst[3]=v.w;
    }
    if (tid < 64) { sM[tid] = -INFINITY; sL[tid] = 0.f; }

    float acc[4][5];
#pragma unroll
    for (int i = 0; i < 4; i++)
#pragma unroll
        for (int j = 0; j < 5; j++) acc[i][j] = 0.f;

    for (int t = 0; t <= qb; t++) {
        __syncthreads();   // prior-iter consumers done; also covers Q/init on t=0
        const float* Kg = Kbase + (size_t)t*64*HDD;
        const float* Vg = Vbase + (size_t)t*64*HDD;
#pragma unroll
        for (int u = 0; u < 5; u++) {
            int lin = tid + u*256;
            int r = lin / 20, cv = lin % 20;
            float4 k4 = *(const float4*)(Kg + r*HDD + cv*4);
            float* dk = &sK[r*SQ_STRIDE + cv*4];
            dk[0]=k4.x; dk[1]=k4.y; dk[2]=k4.z; dk[3]=k4.w;
            float4 v4 = *(const float4*)(Vg + r*HDD + cv*4);
            float* dv = &sV[r*SQ_STRIDE + cv*4];
            dv[0]=v4.x; dv[1]=v4.y; dv[2]=v4.z; dv[3]=v4.w;
        }
        __syncthreads();

        // S = Q K^T  (4x4 patch per thread)
        float sv[4][4];
#pragma unroll
        for (int i = 0; i < 4; i++)
#pragma unroll
            for (int j = 0; j < 4; j++) sv[i][j] = 0.f;
#pragma unroll 4
        for (int d = 0; d < HDD; d++) {
            float qv[4], kv[4];
#pragma unroll
            for (int i = 0; i < 4; i++) qv[i] = sQ[(ty*4+i)*SQ_STRIDE + d];
#pragma unroll
            for (int j = 0; j < 4; j++) kv[j] = sK[(tx*4+j)*SQ_STRIDE + d];
#pragma unroll
            for (int i = 0; i < 4; i++)
#pragma unroll
                for (int j = 0; j < 4; j++)
                    sv[i][j] = fmaf(qv[i], kv[j], sv[i][j]);
        }
        // causal mask + store scores
#pragma unroll
        for (int i = 0; i < 4; i++) {
            int qg = qb*64 + ty*4 + i;
#pragma unroll
            for (int j = 0; j < 4; j++) {
                int kg = t*64 + tx*4 + j;
                sP[(ty*4+i)*SP_STRIDE + tx*4+j] = (kg <= qg) ? sv[i][j] : NEGMASK;
            }
        }
        __syncthreads();

        // online softmax row update
        if (tid < 64) {
            float mold = sM[tid];
            float mnew = mold;
            float* row = &sP[tid*SP_STRIDE];
#pragma unroll 8
            for (int j = 0; j < 64; j++) mnew = fmaxf(mnew, row[j]);
            float alpha = __expf(mold - mnew);
            float sum = 0.f;
#pragma unroll 8
            for (int j = 0; j < 64; j++) {
                float p = __expf(row[j] - mnew);
                row[j] = p;
                sum += p;
            }
            sM[tid] = mnew;
            sL[tid] = sL[tid]*alpha + sum;
            sA[tid] = alpha;
        }
        __syncthreads();

        // rescale accumulators, then O += P @ V  (4x5 patch per thread)
        float al[4];
#pragma unroll
        for (int i = 0; i < 4; i++) al[i] = sA[ty*4+i];
#pragma unroll
        for (int i = 0; i < 4; i++)
#pragma unroll
            for (int j = 0; j < 5; j++) acc[i][j] *= al[i];
#pragma unroll 4
        for (int k = 0; k < 64; k++) {
            float pv[4], vv[5];
#pragma unroll
            for (int i = 0; i < 4; i++) pv[i] = sP[(ty*4+i)*SP_STRIDE + k];
#pragma unroll
            for (int j = 0; j < 5; j++) vv[j] = sV[k*SQ_STRIDE + tx*5 + j];
#pragma unroll
            for (int i = 0; i < 4; i++)
#pragma unroll
                for (int j = 0; j < 5; j++)
                    acc[i][j] = fmaf(pv[i], vv[j], acc[i][j]);
        }
    }

    // normalize and write out to [B,S,H*D]
#pragma unroll
    for (int i = 0; i < 4; i++) {
        int r = ty*4 + i;
        float inv = 1.f / sL[r];
        int sg = qb*64 + r;
        float* dst = g_attn + ((size_t)(b*SS + sg))*HIDD + h*HDD + tx*5;
#pragma unroll
        for (int j = 0; j < 5; j++) dst[j] = acc[i][j] * inv;
    }
}

// ---------------------------------------------------------------------------
extern "C" void kernel_launch(void* const* d_in, const int* in_sizes, int n_in,
                              void* d_out, int out_size)
{
    const float* hs      = (const float*)d_in[0];
    // d_in[1] = mask (deterministically causal; handled analytically)
    const float* scaling = (const float*)d_in[2];
    const float* qkv_w   = (const float*)d_in[3];
    const float* qkv_b   = (const float*)d_in[4];
    const float* o_w     = (const float*)d_in[5];
    const float* o_b     = (const float*)d_in[6];
    float* out = (float*)d_out;

    cudaFuncSetAttribute(attn_kernel,
                         cudaFuncAttributeMaxDynamicSharedMemorySize,
                         ATT_SMEM_BYTES);

    qscale_kernel<<<1, 128>>>(scaling);
    qkv_gemm_kernel<<<dim3(QKVD/128, MR/128), 256>>>(hs, qkv_w, qkv_b);
    attn_kernel<<<dim3(SS/64, NHH, BB), 256, ATT_SMEM_BYTES>>>();
    o_gemm_kernel<<<dim3(HIDD/128, MR/128), 256>>>(out, o_w, o_b);
}

// round 6
// speedup vs baseline: 2.5422x; 2.5422x over previous
#include <cuda_runtime.h>
#include <math.h>

#define BB   4
#define SS   2048
#define HIDD 1280
#define NHH  16
#define NKVV 4
#define HDD  80
#define QKVD 1920
#define MR   (BB*SS)      // 8192
#define NEGMASK (-2.3819763e38f)

// ---- scratch (no allocations allowed: device globals) ----
// q/k/v hold tf32-rounded bit patterns stored as float
__device__ float g_q[(size_t)BB*NHH*SS*HDD];     // [B,H,S,D]  (pre-scaled, tf32 bits)
__device__ float g_k[(size_t)BB*NKVV*SS*HDD];    // [B,KVH,S,D] (tf32 bits)
__device__ float g_v[(size_t)BB*NKVV*SS*HDD];    // [B,KVH,S,D] (tf32 bits)
__device__ float g_attn[(size_t)BB*SS*HIDD];     // [B,S,H*D]  (fp32)
__device__ float g_qscale[HDD];

// ---------------------------------------------------------------------------
__global__ void qscale_kernel(const float* __restrict__ scaling)
{
    int d = threadIdx.x;
    if (d < HDD) {
        float x  = scaling[d];
        float sp = (x > 20.f) ? x : log1pf(expf(x));   // softplus, stable
        g_qscale[d] = 1.442695041f * rsqrtf((float)HDD) * sp;
    }
}

// ---------------------------------------------------------------------------
__device__ __forceinline__ unsigned f2tf(float f)
{
    unsigned r;
    asm("cvt.rna.tf32.f32 %0, %1;" : "=r"(r) : "f"(f));
    return r;
}

__device__ __forceinline__ void mma_tf32(
    float& c0, float& c1, float& c2, float& c3,
    unsigned a0, unsigned a1, unsigned a2, unsigned a3,
    unsigned b0, unsigned b1)
{
    asm volatile(
        "mma.sync.aligned.m16n8k8.row.col.f32.tf32.tf32.f32 "
        "{%0,%1,%2,%3}, {%4,%5,%6,%7}, {%8,%9}, {%0,%1,%2,%3};\n"
        : "+f"(c0), "+f"(c1), "+f"(c2), "+f"(c3)
        : "r"(a0), "r"(a1), "r"(a2), "r"(a3), "r"(b0), "r"(b1));
}

// ---------------------------------------------------------------------------
// tf32 tensor-core GEMM: out = A[M,K] * W[N,K]^T + bias
// 128x128 block tile, BK=16, 8 warps (2M x 4N), warp tile 64x32.
// mode 0: scatter to g_q/g_k/g_v (as tf32 bits).  mode 1: A:=g_attn, write out.
#define BKP 20

__global__ __launch_bounds__(256) void gemm_tf32_kernel(
    const float* __restrict__ A, const float* __restrict__ W,
    const float* __restrict__ bias, float* __restrict__ out, int mode)
{
    __shared__ unsigned As[128][BKP];
    __shared__ unsigned Bs[128][BKP];

    const int tid  = threadIdx.x;
    const int lane = tid & 31;
    const int warp = tid >> 5;
    const int g    = lane >> 2;     // 0..7
    const int t4   = lane & 3;      // 0..3
    const int warpM = warp >> 2;    // 0..1  (64 rows each)
    const int warpN = warp & 3;     // 0..3  (32 cols each)

    const int rowBase = blockIdx.y * 128;
    const int colBase = blockIdx.x * 128;

    const int ldRow = tid >> 1;            // 0..127
    const int ldK   = (tid & 1) * 8;       // 0 or 8

    const float* Asrc = (mode == 1) ? (const float*)g_attn : A;  // device symbol OK here
    const float* Ag = Asrc + (size_t)(rowBase + ldRow) * HIDD + ldK;
    const float* Wg = W    + (size_t)(colBase + ldRow) * HIDD + ldK;

    float c[4][4][4];
#pragma unroll
    for (int mi = 0; mi < 4; mi++)
#pragma unroll
        for (int ni = 0; ni < 4; ni++)
#pragma unroll
            for (int q = 0; q < 4; q++) c[mi][ni][q] = 0.f;

    float4 pa0 = *(const float4*)(Ag);
    float4 pa1 = *(const float4*)(Ag + 4);
    float4 pb0 = *(const float4*)(Wg);
    float4 pb1 = *(const float4*)(Wg + 4);

    for (int k0 = 0; k0 < HIDD; k0 += 16) {
        {
            unsigned* pA = &As[ldRow][ldK];
            pA[0]=f2tf(pa0.x); pA[1]=f2tf(pa0.y); pA[2]=f2tf(pa0.z); pA[3]=f2tf(pa0.w);
            pA[4]=f2tf(pa1.x); pA[5]=f2tf(pa1.y); pA[6]=f2tf(pa1.z); pA[7]=f2tf(pa1.w);
            unsigned* pB = &Bs[ldRow][ldK];
            pB[0]=f2tf(pb0.x); pB[1]=f2tf(pb0.y); pB[2]=f2tf(pb0.z); pB[3]=f2tf(pb0.w);
            pB[4]=f2tf(pb1.x); pB[5]=f2tf(pb1.y); pB[6]=f2tf(pb1.z); pB[7]=f2tf(pb1.w);
        }
        __syncthreads();

        if (k0 + 16 < HIDD) {
            pa0 = *(const float4*)(Ag + k0 + 16);
            pa1 = *(const float4*)(Ag + k0 + 20);
            pb0 = *(const float4*)(Wg + k0 + 16);
            pb1 = *(const float4*)(Wg + k0 + 20);
        }

#pragma unroll
        for (int kk = 0; kk < 16; kk += 8) {
            unsigned b[4][2];
#pragma unroll
            for (int ni = 0; ni < 4; ni++) {
                int n0 = warpN*32 + ni*8 + g;
                b[ni][0] = Bs[n0][kk + t4];
                b[ni][1] = Bs[n0][kk + 4 + t4];
            }
#pragma unroll
            for (int mi = 0; mi < 4; mi++) {
                int r0 = warpM*64 + mi*16 + g;
                unsigned a0 = As[r0    ][kk + t4];
                unsigned a1 = As[r0 + 8][kk + t4];
                unsigned a2 = As[r0    ][kk + 4 + t4];
                unsigned a3 = As[r0 + 8][kk + 4 + t4];
#pragma unroll
                for (int ni = 0; ni < 4; ni++)
                    mma_tf32(c[mi][ni][0], c[mi][ni][1], c[mi][ni][2], c[mi][ni][3],
                             a0, a1, a2, a3, b[ni][0], b[ni][1]);
            }
        }
        __syncthreads();
    }

    // ---- epilogue ----
#pragma unroll
    for (int mi = 0; mi < 4; mi++) {
#pragma unroll
        for (int dr = 0; dr < 2; dr++) {
            int m  = rowBase + warpM*64 + mi*16 + g + dr*8;
            int bb = m >> 11;
            int s  = m & 2047;
#pragma unroll
            for (int ni = 0; ni < 4; ni++) {
#pragma unroll
                for (int dc = 0; dc < 2; dc++) {
                    int   n = colBase + warpN*32 + ni*8 + t4*2 + dc;
                    float v = c[mi][ni][dr*2 + dc] + bias[n];
                    if (mode == 1) {
                        out[(size_t)m*HIDD + n] = v;
                    } else if (n < 1280) {
                        int h = n / HDD, d = n - h*HDD;
                        g_q[(((size_t)(bb*NHH + h))*SS + s)*HDD + d] =
                            __uint_as_float(f2tf(v * g_qscale[d]));
                    } else if (n < 1600) {
                        int cc = n - 1280; int h = cc / HDD, d = cc - h*HDD;
                        g_k[(((size_t)(bb*NKVV + h))*SS + s)*HDD + d] =
                            __uint_as_float(f2tf(v));
                    } else {
                        int cc = n - 1600; int h = cc / HDD, d = cc - h*HDD;
                        g_v[(((size_t)(bb*NKVV + h))*SS + s)*HDD + d] =
                            __uint_as_float(f2tf(v));
                    }
                }
            }
        }
    }
}

// ---------------------------------------------------------------------------
// Flash attention on tf32 mma. 64x64 tiles, online softmax, causal.
// grid: (S/64, NH, B), 256 threads = 8 warps: warpM=warp>>1 (16 rows),
// warpN=warp&1 (32 cols for S, 40 cols for PV).
#define SQS 84   // Q/K/V smem row stride (conflict-free fragment reads)
#define SPS 68   // P smem row stride (conflict-free PV A-frag reads)
#define ATT_SMEM_BYTES (3*64*SQS*4 + 64*SPS*4 + 3*64*4)

__global__ __launch_bounds__(256) void attn_kernel()
{
    extern __shared__ unsigned smu[];
    unsigned* sQ = smu;                      // 64 x 84 (tf32 bits)
    unsigned* sK = sQ + 64*SQS;              // 64 x 84
    unsigned* sV = sK + 64*SQS;              // 64 x 84
    float*    sP = (float*)(sV + 64*SQS);    // 64 x 68
    float*    sM = sP + 64*SPS;
    float*    sL = sM + 64;
    float*    sA = sL + 64;

    const int tid  = threadIdx.x;
    const int lane = tid & 31;
    const int warp = tid >> 5;
    const int g    = lane >> 2;
    const int t4   = lane & 3;
    const int wm   = warp >> 1;    // 0..3
    const int wn   = warp & 1;     // 0..1

    const int qb  = blockIdx.x;
    const int h   = blockIdx.y;
    const int b   = blockIdx.z;
    const int kvh = h >> 2;

    const float* Qg = g_q + (((size_t)(b*NHH  + h  ))*SS + qb*64) * HDD;
    const float* Kb = g_k + (((size_t)(b*NKVV + kvh))*SS) * HDD;
    const float* Vb = g_v + (((size_t)(b*NKVV + kvh))*SS) * HDD;

    // load Q tile (already tf32 bits)
#pragma unroll
    for (int u = 0; u < 5; u++) {
        int lin = tid + u*256;
        int r = lin / 20, cv = lin % 20;
        float4 v = *(const float4*)(Qg + r*HDD + cv*4);
        unsigned* dst = &sQ[r*SQS + cv*4];
        dst[0]=__float_as_uint(v.x); dst[1]=__float_as_uint(v.y);
        dst[2]=__float_as_uint(v.z); dst[3]=__float_as_uint(v.w);
    }
    if (tid < 64) { sM[tid] = -INFINITY; sL[tid] = 0.f; }

    float cO[5][4];
#pragma unroll
    for (int ni = 0; ni < 5; ni++)
#pragma unroll
        for (int q = 0; q < 4; q++) cO[ni][q] = 0.f;

    for (int t = 0; t <= qb; t++) {
        __syncthreads();   // prior PV reads of sV/sP done; Q visible on t=0
        const float* Kg = Kb + (size_t)t*64*HDD;
        const float* Vg = Vb + (size_t)t*64*HDD;
#pragma unroll
        for (int u = 0; u < 5; u++) {
            int lin = tid + u*256;
            int r = lin / 20, cv = lin % 20;
            float4 k4 = *(const float4*)(Kg + r*HDD + cv*4);
            unsigned* dk = &sK[r*SQS + cv*4];
            dk[0]=__float_as_uint(k4.x); dk[1]=__float_as_uint(k4.y);
            dk[2]=__float_as_uint(k4.z); dk[3]=__float_as_uint(k4.w);
            float4 v4 = *(const float4*)(Vg + r*HDD + cv*4);
            unsigned* dv = &sV[r*SQS + cv*4];
            dv[0]=__float_as_uint(v4.x); dv[1]=__float_as_uint(v4.y);
            dv[2]=__float_as_uint(v4.z); dv[3]=__float_as_uint(v4.w);
        }
        __syncthreads();

        // ---- S = Q K^T via mma ----
        float cS[4][4];
#pragma unroll
        for (int ni = 0; ni < 4; ni++)
#pragma unroll
            for (int q = 0; q < 4; q++) cS[ni][q] = 0.f;

        const unsigned* qrow = &sQ[(wm*16 + g)*SQS];
#pragma unroll
        for (int kk = 0; kk < 80; kk += 8) {
            unsigned a0 = qrow[kk + t4];
            unsigned a1 = qrow[8*SQS + kk + t4];
            unsigned a2 = qrow[kk + 4 + t4];
            unsigned a3 = qrow[8*SQS + kk + 4 + t4];
#pragma unroll
            for (int ni = 0; ni < 4; ni++) {
                const unsigned* krow = &sK[(wn*32 + ni*8 + g)*SQS + kk];
                mma_tf32(cS[ni][0], cS[ni][1], cS[ni][2], cS[ni][3],
                         a0, a1, a2, a3, krow[t4], krow[4 + t4]);
            }
        }

        // masked store S -> sP
        const int qg0 = qb*64 + wm*16 + g;
#pragma unroll
        for (int ni = 0; ni < 4; ni++) {
            int kg = t*64 + wn*32 + ni*8 + t4*2;
#pragma unroll
            for (int dr = 0; dr < 2; dr++) {
                int qg = qg0 + dr*8;
                float2 v;
                v.x = (kg     <= qg) ? cS[ni][dr*2 + 0] : NEGMASK;
                v.y = (kg + 1 <= qg) ? cS[ni][dr*2 + 1] : NEGMASK;
                *(float2*)&sP[(wm*16 + g + dr*8)*SPS + wn*32 + ni*8 + t4*2] = v;
            }
        }
        __syncthreads();

        // ---- online softmax: 4 threads per row, quad shuffle reduce ----
        {
            int r = tid >> 2, q4 = tid & 3;
            float* row = &sP[r*SPS + q4*16];
            float mx = row[0];
#pragma unroll
            for (int j = 1; j < 16; j++) mx = fmaxf(mx, row[j]);
            mx = fmaxf(mx, __shfl_xor_sync(0xffffffff, mx, 1));
            mx = fmaxf(mx, __shfl_xor_sync(0xffffffff, mx, 2));
            float mold = sM[r];
            float mnew = fmaxf(mold, mx);
            float sum = 0.f;
#pragma unroll
            for (int j = 0; j < 16; j++) {
                float p = __uint_as_float(f2tf(__expf(row[j] - mnew)));
                row[j] = p;       // store P as tf32 bits
                sum += p;
            }
            sum += __shfl_xor_sync(0xffffffff, sum, 1);
            sum += __shfl_xor_sync(0xffffffff, sum, 2);
            if (q4 == 0) {
                sM[r] = mnew;
                float alpha = __expf(mold - mnew);
                sL[r] = sL[r]*alpha + sum;
                sA[r] = alpha;
            }
        }
        __syncthreads();

        // ---- rescale + O += P V via mma ----
        float al0 = sA[wm*16 + g];
        float al1 = sA[wm*16 + g + 8];
#pragma unroll
        for (int ni = 0; ni < 5; ni++) {
            cO[ni][0] *= al0; cO[ni][1] *= al0;
            cO[ni][2] *= al1; cO[ni][3] *= al1;
        }
        const float* prow = &sP[(wm*16 + g)*SPS];
#pragma unroll
        for (int kk = 0; kk < 64; kk += 8) {
            unsigned a0 = __float_as_uint(prow[kk + t4]);
            unsigned a1 = __float_as_uint(prow[8*SPS + kk + t4]);
            unsigned a2 = __float_as_uint(prow[kk + 4 + t4]);
            unsigned a3 = __float_as_uint(prow[8*SPS + kk + 4 + t4]);
#pragma unroll
            for (int ni = 0; ni < 5; ni++) {
                int nv = wn*40 + ni*8 + g;
                unsigned b0 = sV[(kk + t4)*SQS + nv];
                unsigned b1 = sV[(kk + 4 + t4)*SQS + nv];
                mma_tf32(cO[ni][0], cO[ni][1], cO[ni][2], cO[ni][3],
                         a0, a1, a2, a3, b0, b1);
            }
        }
    }

    // ---- epilogue: normalize, write [B,S,H*D] fp32 ----
    float inv0 = 1.f / sL[wm*16 + g];
    float inv1 = 1.f / sL[wm*16 + g + 8];
    int row0 = qb*64 + wm*16 + g;
    float* o0 = g_attn + ((size_t)(b*SS) + row0)*HIDD + h*HDD + wn*40;
    float* o1 = o0 + (size_t)8*HIDD;
#pragma unroll
    for (int ni = 0; ni < 5; ni++) {
        o0[ni*8 + t4*2    ] = cO[ni][0]*inv0;
        o0[ni*8 + t4*2 + 1] = cO[ni][1]*inv0;
        o1[ni*8 + t4*2    ] = cO[ni][2]*inv1;
        o1[ni*8 + t4*2 + 1] = cO[ni][3]*inv1;
    }
}

// ---------------------------------------------------------------------------
extern "C" void kernel_launch(void* const* d_in, const int* in_sizes, int n_in,
                              void* d_out, int out_size)
{
    const float* hs      = (const float*)d_in[0];
    // d_in[1] = mask (deterministically causal; handled analytically)
    const float* scaling = (const float*)d_in[2];
    const float* qkv_w   = (const float*)d_in[3];
    const float* qkv_b   = (const float*)d_in[4];
    const float* o_w     = (const float*)d_in[5];
    const float* o_b     = (const float*)d_in[6];
    float* out = (float*)d_out;

    cudaFuncSetAttribute(attn_kernel,
                         cudaFuncAttributeMaxDynamicSharedMemorySize,
                         ATT_SMEM_BYTES);

    qscale_kernel<<<1, 128>>>(scaling);
    gemm_tf32_kernel<<<dim3(QKVD/128, MR/128), 256>>>(hs, qkv_w, qkv_b, nullptr, 0);
    attn_kernel<<<dim3(SS/64, NHH, BB), 256, ATT_SMEM_BYTES>>>();
    gemm_tf32_kernel<<<dim3(HIDD/128, MR/128), 256>>>(nullptr, o_w, o_b, out, 1);
}

// round 7
// speedup vs baseline: 2.7385x; 1.0772x over previous
#include <cuda_runtime.h>
#include <math.h>

#define BB   4
#define SS   2048
#define HIDD 1280
#define NHH  16
#define NKVV 4
#define HDD  80
#define QKVD 1920
#define MR   (BB*SS)      // 8192
#define NEGMASK (-2.3819763e38f)

// ---- scratch (no allocations allowed: device globals) ----
// q/k/v hold tf32-rounded bit patterns stored as float
__device__ float g_q[(size_t)BB*NHH*SS*HDD];     // [B,H,S,D]  (pre-scaled, tf32 bits)
__device__ float g_k[(size_t)BB*NKVV*SS*HDD];    // [B,KVH,S,D] (tf32 bits)
__device__ float g_v[(size_t)BB*NKVV*SS*HDD];    // [B,KVH,S,D] (tf32 bits)
__device__ float g_attn[(size_t)BB*SS*HIDD];     // [B,S,H*D]  (fp32)
__device__ float g_qscale[HDD];

// ---------------------------------------------------------------------------
__global__ void qscale_kernel(const float* __restrict__ scaling)
{
    int d = threadIdx.x;
    if (d < HDD) {
        float x  = scaling[d];
        float sp = (x > 20.f) ? x : log1pf(expf(x));   // softplus, stable
        g_qscale[d] = 1.442695041f * rsqrtf((float)HDD) * sp;
    }
}

// ---------------------------------------------------------------------------
__device__ __forceinline__ unsigned f2tf(float f)
{
    unsigned r;
    asm("cvt.rna.tf32.f32 %0, %1;" : "=r"(r) : "f"(f));
    return r;
}

__device__ __forceinline__ void mma_tf32(
    float& c0, float& c1, float& c2, float& c3,
    unsigned a0, unsigned a1, unsigned a2, unsigned a3,
    unsigned b0, unsigned b1)
{
    asm volatile(
        "mma.sync.aligned.m16n8k8.row.col.f32.tf32.tf32.f32 "
        "{%0,%1,%2,%3}, {%4,%5,%6,%7}, {%8,%9}, {%0,%1,%2,%3};\n"
        : "+f"(c0), "+f"(c1), "+f"(c2), "+f"(c3)
        : "r"(a0), "r"(a1), "r"(a2), "r"(a3), "r"(b0), "r"(b1));
}

// ---------------------------------------------------------------------------
// tf32 tensor-core GEMM: out = A[M,K] * W[N,K]^T + bias
// 128x128 block tile, BK=16 double-buffered, 8 warps (2M x 4N), warp 64x32.
// mode 0: scatter to g_q/g_k/g_v (as tf32 bits).  mode 1: A:=g_attn, write out.
#define BKP 20

__global__ __launch_bounds__(256) void gemm_tf32_kernel(
    const float* __restrict__ A, const float* __restrict__ W,
    const float* __restrict__ bias, float* __restrict__ out, int mode)
{
    __shared__ unsigned As[2][128][BKP];
    __shared__ unsigned Bs[2][128][BKP];

    const int tid  = threadIdx.x;
    const int lane = tid & 31;
    const int warp = tid >> 5;
    const int g    = lane >> 2;     // 0..7
    const int t4   = lane & 3;      // 0..3
    const int warpM = warp >> 2;    // 0..1  (64 rows each)
    const int warpN = warp & 3;     // 0..3  (32 cols each)

    const int rowBase = blockIdx.y * 128;
    const int colBase = blockIdx.x * 128;

    const int ldRow = tid >> 1;            // 0..127
    const int ldK   = (tid & 1) * 8;       // 0 or 8

    const float* Asrc = (mode == 1) ? (const float*)g_attn : A;
    const float* Ag = Asrc + (size_t)(rowBase + ldRow) * HIDD + ldK;
    const float* Wg = W    + (size_t)(colBase + ldRow) * HIDD + ldK;

    float c[4][4][4];
#pragma unroll
    for (int mi = 0; mi < 4; mi++)
#pragma unroll
        for (int ni = 0; ni < 4; ni++)
#pragma unroll
            for (int q = 0; q < 4; q++) c[mi][ni][q] = 0.f;

    // stage 0
    float4 pa0 = *(const float4*)(Ag);
    float4 pa1 = *(const float4*)(Ag + 4);
    float4 pb0 = *(const float4*)(Wg);
    float4 pb1 = *(const float4*)(Wg + 4);
    {
        unsigned* pA = &As[0][ldRow][ldK];
        pA[0]=f2tf(pa0.x); pA[1]=f2tf(pa0.y); pA[2]=f2tf(pa0.z); pA[3]=f2tf(pa0.w);
        pA[4]=f2tf(pa1.x); pA[5]=f2tf(pa1.y); pA[6]=f2tf(pa1.z); pA[7]=f2tf(pa1.w);
        unsigned* pB = &Bs[0][ldRow][ldK];
        pB[0]=f2tf(pb0.x); pB[1]=f2tf(pb0.y); pB[2]=f2tf(pb0.z); pB[3]=f2tf(pb0.w);
        pB[4]=f2tf(pb1.x); pB[5]=f2tf(pb1.y); pB[6]=f2tf(pb1.z); pB[7]=f2tf(pb1.w);
    }
    __syncthreads();

    int cur = 0;
    for (int k0 = 16; k0 <= HIDD; k0 += 16) {
        const bool has_next = (k0 < HIDD);
        if (has_next) {
            pa0 = *(const float4*)(Ag + k0);
            pa1 = *(const float4*)(Ag + k0 + 4);
            pb0 = *(const float4*)(Wg + k0);
            pb1 = *(const float4*)(Wg + k0 + 4);
        }

        // compute on stage `cur`
#pragma unroll
        for (int kk = 0; kk < 16; kk += 8) {
            unsigned b[4][2];
#pragma unroll
            for (int ni = 0; ni < 4; ni++) {
                int n0 = warpN*32 + ni*8 + g;
                b[ni][0] = Bs[cur][n0][kk + t4];
                b[ni][1] = Bs[cur][n0][kk + 4 + t4];
            }
#pragma unroll
            for (int mi = 0; mi < 4; mi++) {
                int r0 = warpM*64 + mi*16 + g;
                unsigned a0 = As[cur][r0    ][kk + t4];
                unsigned a1 = As[cur][r0 + 8][kk + t4];
                unsigned a2 = As[cur][r0    ][kk + 4 + t4];
                unsigned a3 = As[cur][r0 + 8][kk + 4 + t4];
#pragma unroll
                for (int ni = 0; ni < 4; ni++)
                    mma_tf32(c[mi][ni][0], c[mi][ni][1], c[mi][ni][2], c[mi][ni][3],
                             a0, a1, a2, a3, b[ni][0], b[ni][1]);
            }
        }

        if (has_next) {
            int nxt = cur ^ 1;
            unsigned* pA = &As[nxt][ldRow][ldK];
            pA[0]=f2tf(pa0.x); pA[1]=f2tf(pa0.y); pA[2]=f2tf(pa0.z); pA[3]=f2tf(pa0.w);
            pA[4]=f2tf(pa1.x); pA[5]=f2tf(pa1.y); pA[6]=f2tf(pa1.z); pA[7]=f2tf(pa1.w);
            unsigned* pB = &Bs[nxt][ldRow][ldK];
            pB[0]=f2tf(pb0.x); pB[1]=f2tf(pb0.y); pB[2]=f2tf(pb0.z); pB[3]=f2tf(pb0.w);
            pB[4]=f2tf(pb1.x); pB[5]=f2tf(pb1.y); pB[6]=f2tf(pb1.z); pB[7]=f2tf(pb1.w);
        }
        __syncthreads();
        cur ^= 1;
    }

    // ---- epilogue ----
#pragma unroll
    for (int mi = 0; mi < 4; mi++) {
#pragma unroll
        for (int dr = 0; dr < 2; dr++) {
            int m  = rowBase + warpM*64 + mi*16 + g + dr*8;
            int bb = m >> 11;
            int s  = m & 2047;
#pragma unroll
            for (int ni = 0; ni < 4; ni++) {
#pragma unroll
                for (int dc = 0; dc < 2; dc++) {
                    int   n = colBase + warpN*32 + ni*8 + t4*2 + dc;
                    float v = c[mi][ni][dr*2 + dc] + bias[n];
                    if (mode == 1) {
                        out[(size_t)m*HIDD + n] = v;
                    } else if (n < 1280) {
                        int h = n / HDD, d = n - h*HDD;
                        g_q[(((size_t)(bb*NHH + h))*SS + s)*HDD + d] =
                            __uint_as_float(f2tf(v * g_qscale[d]));
                    } else if (n < 1600) {
                        int cc = n - 1280; int h = cc / HDD, d = cc - h*HDD;
                        g_k[(((size_t)(bb*NKVV + h))*SS + s)*HDD + d] =
                            __uint_as_float(f2tf(v));
                    } else {
                        int cc = n - 1600; int h = cc / HDD, d = cc - h*HDD;
                        g_v[(((size_t)(bb*NKVV + h))*SS + s)*HDD + d] =
                            __uint_as_float(f2tf(v));
                    }
                }
            }
        }
    }
}

// ---------------------------------------------------------------------------
// Flash attention on tf32 mma. Q tile 128 rows, K tile 64, online softmax.
// 8 warps; warp w owns rows [w*16, w*16+16) for ALL 64/80 cols ->
// softmax fully in registers (quad shfl only). sP round trip only for PV
// A-fragment relayout.  grid: (S/128, NH, B), 256 threads.
#define QT  128
#define SQS 84   // Q/K/V smem row stride (conflict-free fragment reads)
#define SPS 68   // P smem row stride (conflict-free PV A-frag reads)
#define ATT_SMEM_BYTES ((QT*SQS + 2*64*SQS + QT*SPS)*4)

__global__ __launch_bounds__(256) void attn_kernel()
{
    extern __shared__ unsigned smu[];
    unsigned* sQ = smu;                      // 128 x 84 (tf32 bits)
    unsigned* sK = sQ + QT*SQS;              // 64 x 84
    unsigned* sV = sK + 64*SQS;              // 64 x 84
    float*    sP = (float*)(sV + 64*SQS);    // 128 x 68

    const int tid  = threadIdx.x;
    const int lane = tid & 31;
    const int warp = tid >> 5;
    const int g    = lane >> 2;
    const int t4   = lane & 3;

    const int qb  = blockIdx.x;
    const int h   = blockIdx.y;
    const int b   = blockIdx.z;
    const int kvh = h >> 2;

    const float* Qg = g_q + (((size_t)(b*NHH  + h  ))*SS + qb*QT) * HDD;
    const float* Kb = g_k + (((size_t)(b*NKVV + kvh))*SS) * HDD;
    const float* Vb = g_v + (((size_t)(b*NKVV + kvh))*SS) * HDD;

    // load Q tile: 128*20 float4 = 2560, 10 per thread
#pragma unroll
    for (int u = 0; u < 10; u++) {
        int lin = tid + u*256;
        int r = lin / 20, cv = lin % 20;
        float4 v = *(const float4*)(Qg + r*HDD + cv*4);
        unsigned* dst = &sQ[r*SQS + cv*4];
        dst[0]=__float_as_uint(v.x); dst[1]=__float_as_uint(v.y);
        dst[2]=__float_as_uint(v.z); dst[3]=__float_as_uint(v.w);
    }

    float cO[10][4];
#pragma unroll
    for (int ni = 0; ni < 10; ni++)
#pragma unroll
        for (int q = 0; q < 4; q++) cO[ni][q] = 0.f;

    float m0 = -INFINITY, m1 = -INFINITY, l0 = 0.f, l1 = 0.f;
    const int r0g  = qb*QT + warp*16 + g;        // global row (low half)
    const int wtop = qb*QT + warp*16 + 15;       // warp's last row

    const int tmax = 2*qb + 1;
    for (int t = 0; t <= tmax; t++) {
        __syncthreads();   // prev-iter smem consumers done (covers Q on t=0)
        const float* Kg = Kb + (size_t)t*64*HDD;
        const float* Vg = Vb + (size_t)t*64*HDD;
#pragma unroll
        for (int u = 0; u < 5; u++) {
            int lin = tid + u*256;
            int r = lin / 20, cv = lin % 20;
            float4 k4 = *(const float4*)(Kg + r*HDD + cv*4);
            unsigned* dk = &sK[r*SQS + cv*4];
            dk[0]=__float_as_uint(k4.x); dk[1]=__float_as_uint(k4.y);
            dk[2]=__float_as_uint(k4.z); dk[3]=__float_as_uint(k4.w);
            float4 v4 = *(const float4*)(Vg + r*HDD + cv*4);
            unsigned* dv = &sV[r*SQS + cv*4];
            dv[0]=__float_as_uint(v4.x); dv[1]=__float_as_uint(v4.y);
            dv[2]=__float_as_uint(v4.z); dv[3]=__float_as_uint(v4.w);
        }
        __syncthreads();

        const bool active = (t*64 <= wtop);   // any unmasked key for this warp?
        if (active) {
            // ---- S = Q K^T ----
            float cS[8][4];
#pragma unroll
            for (int ni = 0; ni < 8; ni++)
#pragma unroll
                for (int q = 0; q < 4; q++) cS[ni][q] = 0.f;

            const unsigned* qrow = &sQ[(warp*16 + g)*SQS];
#pragma unroll
            for (int kk = 0; kk < 80; kk += 8) {
                unsigned a0 = qrow[kk + t4];
                unsigned a1 = qrow[8*SQS + kk + t4];
                unsigned a2 = qrow[kk + 4 + t4];
                unsigned a3 = qrow[8*SQS + kk + 4 + t4];
#pragma unroll
                for (int ni = 0; ni < 8; ni++) {
                    const unsigned* krow = &sK[(ni*8 + g)*SQS + kk];
                    mma_tf32(cS[ni][0], cS[ni][1], cS[ni][2], cS[ni][3],
                             a0, a1, a2, a3, krow[t4], krow[4 + t4]);
                }
            }

            // ---- mask + in-register online softmax ----
            float mx0 = NEGMASK, mx1 = NEGMASK;
#pragma unroll
            for (int ni = 0; ni < 8; ni++) {
#pragma unroll
                for (int dc = 0; dc < 2; dc++) {
                    int kg = t*64 + ni*8 + t4*2 + dc;
                    if (kg > r0g)     cS[ni][dc]     = NEGMASK;
                    if (kg > r0g + 8) cS[ni][2 + dc] = NEGMASK;
                    mx0 = fmaxf(mx0, cS[ni][dc]);
                    mx1 = fmaxf(mx1, cS[ni][2 + dc]);
                }
            }
            mx0 = fmaxf(mx0, __shfl_xor_sync(0xffffffff, mx0, 1));
            mx0 = fmaxf(mx0, __shfl_xor_sync(0xffffffff, mx0, 2));
            mx1 = fmaxf(mx1, __shfl_xor_sync(0xffffffff, mx1, 1));
            mx1 = fmaxf(mx1, __shfl_xor_sync(0xffffffff, mx1, 2));

            float m0n = fmaxf(m0, mx0);
            float m1n = fmaxf(m1, mx1);
            float s0 = 0.f, s1 = 0.f;
            float* prow = &sP[(warp*16 + g)*SPS];
#pragma unroll
            for (int ni = 0; ni < 8; ni++) {
                float p00 = __uint_as_float(f2tf(__expf(cS[ni][0] - m0n)));
                float p01 = __uint_as_float(f2tf(__expf(cS[ni][1] - m0n)));
                float p10 = __uint_as_float(f2tf(__expf(cS[ni][2] - m1n)));
                float p11 = __uint_as_float(f2tf(__expf(cS[ni][3] - m1n)));
                s0 += p00 + p01;
                s1 += p10 + p11;
                *(float2*)&prow[ni*8 + t4*2]           = make_float2(p00, p01);
                *(float2*)&prow[8*SPS + ni*8 + t4*2]   = make_float2(p10, p11);
            }
            s0 += __shfl_xor_sync(0xffffffff, s0, 1);
            s0 += __shfl_xor_sync(0xffffffff, s0, 2);
            s1 += __shfl_xor_sync(0xffffffff, s1, 1);
            s1 += __shfl_xor_sync(0xffffffff, s1, 2);

            float al0 = __expf(m0 - m0n);
            float al1 = __expf(m1 - m1n);
            l0 = l0*al0 + s0;
            l1 = l1*al1 + s1;
            m0 = m0n; m1 = m1n;
#pragma unroll
            for (int ni = 0; ni < 10; ni++) {
                cO[ni][0] *= al0; cO[ni][1] *= al0;
                cO[ni][2] *= al1; cO[ni][3] *= al1;
            }
        }
        __syncthreads();   // sP visible (warp reads only its own rows, but keep
                           // global ordering vs next iter's K/V overwrite)
        if (active) {
            // ---- O += P V ----
            const float* prow = &sP[(warp*16 + g)*SPS];
#pragma unroll
            for (int kk = 0; kk < 64; kk += 8) {
                unsigned a0 = __float_as_uint(prow[kk + t4]);
                unsigned a1 = __float_as_uint(prow[8*SPS + kk + t4]);
                unsigned a2 = __float_as_uint(prow[kk + 4 + t4]);
                unsigned a3 = __float_as_uint(prow[8*SPS + kk + 4 + t4]);
#pragma unroll
                for (int ni = 0; ni < 10; ni++) {
                    unsigned b0 = sV[(kk + t4)*SQS + ni*8 + g];
                    unsigned b1 = sV[(kk + 4 + t4)*SQS + ni*8 + g];
                    mma_tf32(cO[ni][0], cO[ni][1], cO[ni][2], cO[ni][3],
                             a0, a1, a2, a3, b0, b1);
                }
            }
        }
    }

    // ---- epilogue: normalize, write [B,S,H*D] fp32 ----
    float inv0 = 1.f / l0;
    float inv1 = 1.f / l1;
    int r0 = qb*QT + warp*16 + g;
    float* o0 = g_attn + ((size_t)(b*SS) + r0)*HIDD + h*HDD;
    float* o1 = o0 + (size_t)8*HIDD;
#pragma unroll
    for (int ni = 0; ni < 10; ni++) {
        o0[ni*8 + t4*2    ] = cO[ni][0]*inv0;
        o0[ni*8 + t4*2 + 1] = cO[ni][1]*inv0;
        o1[ni*8 + t4*2    ] = cO[ni][2]*inv1;
        o1[ni*8 + t4*2 + 1] = cO[ni][3]*inv1;
    }
}

// ---------------------------------------------------------------------------
extern "C" void kernel_launch(void* const* d_in, const int* in_sizes, int n_in,
                              void* d_out, int out_size)
{
    const float* hs      = (const float*)d_in[0];
    // d_in[1] = mask (deterministically causal; handled analytically)
    const float* scaling = (const float*)d_in[2];
    const float* qkv_w   = (const float*)d_in[3];
    const float* qkv_b   = (const float*)d_in[4];
    const float* o_w     = (const float*)d_in[5];
    const float* o_b     = (const float*)d_in[6];
    float* out = (float*)d_out;

    cudaFuncSetAttribute(attn_kernel,
                         cudaFuncAttributeMaxDynamicSharedMemorySize,
                         ATT_SMEM_BYTES);

    qscale_kernel<<<1, 128>>>(scaling);
    gemm_tf32_kernel<<<dim3(QKVD/128, MR/128), 256>>>(hs, qkv_w, qkv_b, nullptr, 0);
    attn_kernel<<<dim3(SS/QT, NHH, BB), 256, ATT_SMEM_BYTES>>>();
    gemm_tf32_kernel<<<dim3(HIDD/128, MR/128), 256>>>(nullptr, o_w, o_b, out, 1);
}